// round 8
// baseline (speedup 1.0000x reference)
#include <cuda_runtime.h>

// Unpool_LS: 2x2 block learned-sparsity unpool.
// x0: [8,256,256,64] f32, x1: [8,128,128,64] f32
// outputs concatenated into d_out:
//   out0 [8,256,256,64], repl [8,128,128,64], out3 [8,256,256,64]
//
// R6: register-diet version. Outputs overwrite inputs in place:
//   - out0 values overwrite a0..a3 (v kept only transiently per lane)
//   - repl overwrites pv
//   - out3 reconstructed at store time from a packed 16-bit mask + frac[4]
// __launch_bounds__(256,6) caps regs at 42 -> 48 warps/SM (vs 36 before).
// Streaming cache hints (__ldcs/__stcs): every byte touched exactly once.

#define BB   8
#define HH   256
#define WW   256
#define CC   64
#define hh2  128
#define ww2  128
#define C4   (CC / 4)   // 16 float4 per position

__global__ void __launch_bounds__(256, 6)
unpool_ls_kernel(const float4 *__restrict__ x0,
                 const float4 *__restrict__ x1,
                 float4 *__restrict__ out0,
                 float4 *__restrict__ out1,
                 float4 *__restrict__ out2) {
    int t = blockIdx.x * blockDim.x + threadIdx.x;   // [0, 131072*16)
    int cq  = t & (C4 - 1);      // channel quad 0..15
    int blk = t >> 4;            // linear (b,h,w) block index, 0..131071

    int w = blk & (ww2 - 1);
    int h = (blk >> 7) & (hh2 - 1);
    int b = blk >> 14;

    int pos = ((b * HH + 2 * h) * WW + 2 * w);       // position index in x0
    int i00 = pos * C4 + cq;
    int i01 = i00 + C4;
    int i10 = i00 + WW * C4;
    int i11 = i10 + C4;
    int ip  = blk * C4 + cq;

    // Front-batched streaming loads (MLP=5)
    float4 a0 = __ldcs(&x0[i00]);
    float4 a1 = __ldcs(&x0[i01]);
    float4 a2 = __ldcs(&x0[i10]);
    float4 a3 = __ldcs(&x0[i11]);
    float4 pv = __ldcs(&x1[ip]);

    float *pa0 = (float*)&a0;
    float *pa1 = (float*)&a1;
    float *pa2 = (float*)&a2;
    float *pa3 = (float*)&a3;
    float *ppv = (float*)&pv;

    unsigned mask = 0;     // bit (ln*4 + pos): position replaced in lane ln
    float frac[4];

#pragma unroll
    for (int ln = 0; ln < 4; ln++) {
        float v0 = pa0[ln], v1 = pa1[ln], v2 = pa2[ln], v3 = pa3[ln];

        // Stable descending rank: rank[i] = #{j: v[j] > v[i]} + #{j<i: v[j] == v[i]}
        int r0 = (int)(v1 > v0) + (int)(v2 > v0) + (int)(v3 > v0);
        int r1 = (int)(v0 >= v1) + (int)(v2 > v1) + (int)(v3 > v1);
        int r2 = (int)(v0 >= v2) + (int)(v1 >= v2) + (int)(v3 > v2);
        int r3 = (int)(v0 >= v3) + (int)(v1 >= v3) + (int)(v2 >= v3);

        // Scatter into sorted-descending order
        float sv0, sv1, sv2, sv3;
        float sv[4];
#pragma unroll
        for (int q = 0; q < 4; q++) sv[q] = 0.0f;
        sv[r0] = v0; sv[r1] = v1; sv[r2] = v2; sv[r3] = v3;
        sv0 = sv[0]; sv1 = sv[1]; sv2 = sv[2]; sv3 = sv[3];

        // avg[k] = (prefix_sum + x1)/(k+2); first-max argmax (strict >)
        float x1v = ppv[ln];
        float s  = sv0;
        float best = (s + x1v) * 0.5f;          // /2 exact: *0.5f is IEEE-identical
        int   kb = 0;
        s += sv1;
        { float avg = (s + x1v) / 3.0f; if (avg > best) { best = avg; kb = 1; } }
        s += sv2;
        { float avg = (s + x1v) * 0.25f; if (avg > best) { best = avg; kb = 2; } }
        s += sv3;
        { float avg = (s + x1v) / 5.0f; if (avg > best) { best = avg; kb = 3; } }

        ppv[ln] = best;                          // repl overwrites x1 value
        frac[ln] = (float)(kb + 1) / (float)(kb + 2);

        bool m0 = r0 <= kb, m1 = r1 <= kb, m2 = r2 <= kb, m3 = r3 <= kb;
        pa0[ln] = m0 ? best : v0;                // out0 overwrites input regs
        pa1[ln] = m1 ? best : v1;
        pa2[ln] = m2 ? best : v2;
        pa3[ln] = m3 ? best : v3;
        mask |= ((unsigned)m0 | ((unsigned)m1 << 1) |
                 ((unsigned)m2 << 2) | ((unsigned)m3 << 3)) << (ln * 4);
    }

    // out0 (replaced-value map)
    __stcs(&out0[i00], a0);
    __stcs(&out0[i01], a1);
    __stcs(&out0[i10], a2);
    __stcs(&out0[i11], a3);

    // repl
    __stcs(&out1[ip], pv);

    // out3 (fraction map), reconstructed from mask + frac
#pragma unroll
    for (int p = 0; p < 4; p++) {
        float4 f;
        f.x = (mask >> (0 * 4 + p)) & 1u ? frac[0] : 1.0f;
        f.y = (mask >> (1 * 4 + p)) & 1u ? frac[1] : 1.0f;
        f.z = (mask >> (2 * 4 + p)) & 1u ? frac[2] : 1.0f;
        f.w = (mask >> (3 * 4 + p)) & 1u ? frac[3] : 1.0f;
        int idx = (p == 0) ? i00 : (p == 1) ? i01 : (p == 2) ? i10 : i11;
        __stcs(&out2[idx], f);
    }
}

extern "C" void kernel_launch(void* const* d_in, const int* in_sizes, int n_in,
                              void* d_out, int out_size) {
    const float* x0 = (const float*)d_in[0];
    const float* x1 = (const float*)d_in[1];
    float* out = (float*)d_out;

    const size_t N0 = (size_t)BB * HH * WW * CC;     // 33554432
    const size_t N1 = (size_t)BB * hh2 * ww2 * CC;   // 8388608

    float* out0 = out;
    float* out1 = out + N0;
    float* out2 = out + N0 + N1;

    const int total_threads = (BB * hh2 * ww2) * C4; // 2097152
    const int block = 256;
    const int grid = total_threads / block;          // 8192

    unpool_ls_kernel<<<grid, block>>>((const float4*)x0, (const float4*)x1,
                                      (float4*)out0, (float4*)out1, (float4*)out2);
}